// round 7
// baseline (speedup 1.0000x reference)
#include <cuda_runtime.h>

#define N_NODES 768
#define INP     256
#define H       4
#define FH      64
#define OUTD    256   // H*FH
#define NSPLIT  6
#define JSPAN   (N_NODES / NSPLIT)   // 128
#define TI      16
#define TJ      64
#define WXJ_PAD 70

typedef unsigned long long u64;

// Scratch (no cudaMalloc allowed)
__device__ float g_Wx[N_NODES * OUTD];
__device__ float g_E[N_NODES * H];
__device__ float g_pm[N_NODES * H][NSPLIT];
__device__ float g_ps[N_NODES * H][NSPLIT];
__device__ float g_pacc[N_NODES * H][NSPLIT][FH];

// ---------------- packed f32x2 helpers (sm_103a) ----------------
__device__ __forceinline__ u64 pk2(float x, float y) {
    u64 r; asm("mov.b64 %0,{%1,%2};" : "=l"(r) : "f"(x), "f"(y)); return r;
}
__device__ __forceinline__ float2 upk2(u64 v) {
    float2 r; asm("mov.b64 {%0,%1},%2;" : "=f"(r.x), "=f"(r.y) : "l"(v)); return r;
}
__device__ __forceinline__ void mac_abs2(u64& acc, u64 av, u64 wi, u64 sj) {
    u64 t;
    asm("add.rn.f32x2 %0,%1,%2;" : "=l"(t) : "l"(wi), "l"(sj));
    asm("and.b64 %0,%0,0x7FFFFFFF7FFFFFFF;" : "+l"(t));
    asm("fma.rn.f32x2 %0,%1,%2,%0;" : "+l"(acc) : "l"(av), "l"(t));
}
__device__ __forceinline__ void fma2(u64& acc, u64 a, u64 b) {
    asm("fma.rn.f32x2 %0,%1,%2,%0;" : "+l"(acc) : "l"(a), "l"(b));
}
__device__ __forceinline__ void mul2(u64& acc, u64 a) {
    asm("mul.rn.f32x2 %0,%0,%1;" : "+l"(acc) : "l"(a));
}
// LDS.128 into two u64 (one broadcast feeds two packed operands)
__device__ __forceinline__ void lds_v2u64(u64& a, u64& b, const void* p) {
    unsigned s = (unsigned)__cvta_generic_to_shared(p);
    asm("ld.shared.v2.u64 {%0,%1}, [%2];" : "=l"(a), "=l"(b) : "r"(s));
}

// ---------------------------------------------------------------------------
// GEMM: Wx = x @ W^T.  BM=16, BN=64(=1 head), BK=32, 256 thr.
// Grid (H, 48) = 192 blocks (2x the old 96 -> ~10 warps/SM).
// Register-prefetch double buffering. Fused E epilogue.
// Thread (ty=tid/16, tx=tid%16) computes row ty, cols tx*4..tx*4+3.
// ---------------------------------------------------------------------------
__global__ __launch_bounds__(256) void gemm_kernel(const float* __restrict__ x,
                                                   const float* __restrict__ W,
                                                   const float* __restrict__ a) {
    __shared__ float As[32][20];   // [k][m], pad to 20
    __shared__ float Bs[32][68];   // [k][n]
    const int tid = threadIdx.x;
    const int m0 = blockIdx.y * 16;
    const int h  = blockIdx.x;
    const int n0 = h * 64;

    const int lr = tid / 8;        // 0..31
    const int lc = tid % 8;        // float4 col
    const int tx = tid % 16;       // n quad
    const int ty = tid / 16;       // m row (0..15)
    float4 acc = make_float4(0.f, 0.f, 0.f, 0.f);

    float4 px, pw0, pw1;
    if (tid < 128)
        px = *reinterpret_cast<const float4*>(&x[(m0 + lr) * INP + lc * 4]);
    pw0 = *reinterpret_cast<const float4*>(&W[(n0 + lr) * INP + lc * 4]);
    pw1 = *reinterpret_cast<const float4*>(&W[(n0 + lr + 32) * INP + lc * 4]);

    #pragma unroll 1
    for (int it = 0; it < 8; it++) {
        __syncthreads();
        if (tid < 128) {
            As[lc * 4 + 0][lr] = px.x; As[lc * 4 + 1][lr] = px.y;
            As[lc * 4 + 2][lr] = px.z; As[lc * 4 + 3][lr] = px.w;
        }
        Bs[lc * 4 + 0][lr] = pw0.x; Bs[lc * 4 + 1][lr] = pw0.y;
        Bs[lc * 4 + 2][lr] = pw0.z; Bs[lc * 4 + 3][lr] = pw0.w;
        Bs[lc * 4 + 0][lr + 32] = pw1.x; Bs[lc * 4 + 1][lr + 32] = pw1.y;
        Bs[lc * 4 + 2][lr + 32] = pw1.z; Bs[lc * 4 + 3][lr + 32] = pw1.w;
        __syncthreads();
        if (it < 7) {
            const int k0 = (it + 1) * 32;
            if (tid < 128)
                px = *reinterpret_cast<const float4*>(&x[(m0 + lr) * INP + k0 + lc * 4]);
            pw0 = *reinterpret_cast<const float4*>(&W[(n0 + lr) * INP + k0 + lc * 4]);
            pw1 = *reinterpret_cast<const float4*>(&W[(n0 + lr + 32) * INP + k0 + lc * 4]);
        }
        #pragma unroll
        for (int k = 0; k < 32; k++) {
            const float av = As[k][ty];
            float4 bv = *reinterpret_cast<const float4*>(&Bs[k][tx * 4]);
            acc.x += av * bv.x; acc.y += av * bv.y;
            acc.z += av * bv.z; acc.w += av * bv.w;
        }
    }

    const int m = m0 + ty;
    *reinterpret_cast<float4*>(&g_Wx[m * OUTD + n0 + tx * 4]) = acc;

    // E epilogue: reduce dot(a4, acc) over the 16 lanes sharing ty
    float4 a4v = *reinterpret_cast<const float4*>(&a[tx * 4]);
    float ev = a4v.x * acc.x + a4v.y * acc.y + a4v.z * acc.z + a4v.w * acc.w;
    #pragma unroll
    for (int off = 1; off < 16; off <<= 1)
        ev += __shfl_xor_sync(0xffffffffu, ev, off);
    if (tx == 0) g_E[m * H + h] = ev;
}

// ---------------------------------------------------------------------------
// Split-KV flash attention. Block = (16 i-rows, head, j-split of 128).
// 128 threads, warp w owns rows {w, w+4, w+8, w+12}. Partial (m,s,acc) out.
// ---------------------------------------------------------------------------
__global__ __launch_bounds__(128) void attn_kernel(const int* __restrict__ adj,
                                                   const float* __restrict__ a) {
    __shared__ __align__(16) float wxj[TJ][WXJ_PAD];   // 17.9 KB
    __shared__ float4 wi4[2][4][32];                   // 4 KB: [q][warp][k] = 2 rows' f-pair
    __shared__ float4 p_ab[4][TJ];                     // 4 KB: (pa,pa,pb,pb)
    __shared__ float4 p_cd[4][TJ];                     // 4 KB
    __shared__ u64    av2[FH / 2];
    __shared__ float  e06s[JSPAN];                     // 0.6*E_j for this split

    const int tid  = threadIdx.x;
    const int w    = tid / 32;
    const int lane = tid % 32;
    const int h    = blockIdx.y;
    const int iblk = blockIdx.x / NSPLIT;
    const int sp   = blockIdx.x % NSPLIT;
    const int i0   = iblk * TI;
    const int jbase = sp * JSPAN;

    // ---- stage per-block constants ----
    for (int id = tid; id < 256; id += 128) {          // wi4: 256 float4
        const int q = id >> 7, rem = id & 127;
        const int w2 = rem >> 5, k = rem & 31;
        const int r0 = w2 + 8 * q, r1 = r0 + 4;
        float2 lo = *reinterpret_cast<const float2*>(&g_Wx[(i0 + r0) * OUTD + h * FH + 2 * k]);
        float2 hi = *reinterpret_cast<const float2*>(&g_Wx[(i0 + r1) * OUTD + h * FH + 2 * k]);
        wi4[q][w2][k] = make_float4(lo.x, lo.y, hi.x, hi.y);
    }
    if (tid < FH / 2)
        av2[tid] = *reinterpret_cast<const u64*>(&a[2 * tid]);
    if (tid < JSPAN)
        e06s[tid] = 0.6f * g_E[(jbase + tid) * H + h];

    const int rA = i0 + w, rB = rA + 4, rC = rA + 8, rD = rA + 12;
    const float eiA = 0.6f * g_E[rA * H + h];
    const float eiB = 0.6f * g_E[rB * H + h];
    const float eiC = 0.6f * g_E[rC * H + h];
    const float eiD = 0.6f * g_E[rD * H + h];
    const int* adjA = &adj[rA * N_NODES + jbase];
    const int* adjB = &adj[rB * N_NODES + jbase];
    const int* adjC = &adj[rC * N_NODES + jbase];
    const int* adjD = &adj[rD * N_NODES + jbase];

    float mA = -1e30f, sA = 0.f, mB = -1e30f, sB = 0.f;
    float mC = -1e30f, sC = 0.f, mD = -1e30f, sD = 0.f;
    u64 accA = 0, accB = 0, accC = 0, accD = 0;

    #pragma unroll 1
    for (int jt = 0; jt < JSPAN; jt += TJ) {
        __syncthreads();
        // ---- stage wxj tile (64 rows x 64 f): 1024 float4, 8/thread ----
        #pragma unroll
        for (int r = 0; r < 8; r++) {
            const int id = tid + r * 128;
            const int jj = id / 16, c4 = id % 16;
            float4 v = *reinterpret_cast<const float4*>(
                &g_Wx[(jbase + jt + jj) * OUTD + h * FH + c4 * 4]);
            *reinterpret_cast<float2*>(&wxj[jj][c4 * 4])     = make_float2(v.x, v.y);
            *reinterpret_cast<float2*>(&wxj[jj][c4 * 4 + 2]) = make_float2(v.z, v.w);
        }
        __syncthreads();

        // ---- e-phase: lane j-cols (jt+lane, jt+32+lane) x 4 rows ----
        const u64* wj0 = reinterpret_cast<const u64*>(&wxj[lane][0]);
        const u64* wj1 = reinterpret_cast<const u64*>(&wxj[lane + 32][0]);
        u64 eA0 = 0, eA1 = 0, eB0 = 0, eB1 = 0;
        u64 eC0 = 0, eC1 = 0, eD0 = 0, eD1 = 0;
        #pragma unroll
        for (int k = 0; k < 32; k++) {
            const u64 avk = av2[k];
            u64 wa, wb, wc, wd;
            lds_v2u64(wa, wb, &wi4[0][w][k]);
            lds_v2u64(wc, wd, &wi4[1][w][k]);
            const u64 j0 = wj0[k];
            const u64 j1 = wj1[k];
            mac_abs2(eA0, avk, wa, j0);  mac_abs2(eA1, avk, wa, j1);
            mac_abs2(eB0, avk, wb, j0);  mac_abs2(eB1, avk, wb, j1);
            mac_abs2(eC0, avk, wc, j0);  mac_abs2(eC1, avk, wc, j1);
            mac_abs2(eD0, avk, wd, j0);  mac_abs2(eD1, avk, wd, j1);
        }
        const float ej0 = e06s[jt + lane], ej1 = e06s[jt + 32 + lane];
        float2 f;
        f = upk2(eA0); float e_A0 = eiA + ej0 + 0.4f * (f.x + f.y);
        f = upk2(eA1); float e_A1 = eiA + ej1 + 0.4f * (f.x + f.y);
        f = upk2(eB0); float e_B0 = eiB + ej0 + 0.4f * (f.x + f.y);
        f = upk2(eB1); float e_B1 = eiB + ej1 + 0.4f * (f.x + f.y);
        f = upk2(eC0); float e_C0 = eiC + ej0 + 0.4f * (f.x + f.y);
        f = upk2(eC1); float e_C1 = eiC + ej1 + 0.4f * (f.x + f.y);
        f = upk2(eD0); float e_D0 = eiD + ej0 + 0.4f * (f.x + f.y);
        f = upk2(eD1); float e_D1 = eiD + ej1 + 0.4f * (f.x + f.y);
        if (adjA[jt + lane]      == 0) e_A0 = -1e30f;
        if (adjA[jt + 32 + lane] == 0) e_A1 = -1e30f;
        if (adjB[jt + lane]      == 0) e_B0 = -1e30f;
        if (adjB[jt + 32 + lane] == 0) e_B1 = -1e30f;
        if (adjC[jt + lane]      == 0) e_C0 = -1e30f;
        if (adjC[jt + 32 + lane] == 0) e_C1 = -1e30f;
        if (adjD[jt + lane]      == 0) e_D0 = -1e30f;
        if (adjD[jt + 32 + lane] == 0) e_D1 = -1e30f;

        // ---- online softmax update, 4 rows ----
        float tA = fmaxf(e_A0, e_A1), tB = fmaxf(e_B0, e_B1);
        float tC = fmaxf(e_C0, e_C1), tD = fmaxf(e_D0, e_D1);
        #pragma unroll
        for (int off = 16; off > 0; off >>= 1) {
            tA = fmaxf(tA, __shfl_xor_sync(0xffffffffu, tA, off));
            tB = fmaxf(tB, __shfl_xor_sync(0xffffffffu, tB, off));
            tC = fmaxf(tC, __shfl_xor_sync(0xffffffffu, tC, off));
            tD = fmaxf(tD, __shfl_xor_sync(0xffffffffu, tD, off));
        }
        const float nA = fmaxf(mA, tA), nB = fmaxf(mB, tB);
        const float nC = fmaxf(mC, tC), nD = fmaxf(mD, tD);
        const float scA = __expf(mA - nA), scB = __expf(mB - nB);
        const float scC = __expf(mC - nC), scD = __expf(mD - nD);
        const float pA0 = __expf(e_A0 - nA), pA1 = __expf(e_A1 - nA);
        const float pB0 = __expf(e_B0 - nB), pB1 = __expf(e_B1 - nB);
        const float pC0 = __expf(e_C0 - nC), pC1 = __expf(e_C1 - nC);
        const float pD0 = __expf(e_D0 - nD), pD1 = __expf(e_D1 - nD);
        sA = sA * scA + pA0 + pA1;  sB = sB * scB + pB0 + pB1;
        sC = sC * scC + pC0 + pC1;  sD = sD * scD + pD0 + pD1;
        mul2(accA, pk2(scA, scA));  mul2(accB, pk2(scB, scB));
        mul2(accC, pk2(scC, scC));  mul2(accD, pk2(scD, scD));
        mA = nA; mB = nB; mC = nC; mD = nD;

        p_ab[w][lane]      = make_float4(pA0, pA0, pB0, pB0);
        p_ab[w][lane + 32] = make_float4(pA1, pA1, pB1, pB1);
        p_cd[w][lane]      = make_float4(pC0, pC0, pD0, pD0);
        p_cd[w][lane + 32] = make_float4(pC1, pC1, pD1, pD1);
        __syncwarp();

        // ---- aggregation: one wv read feeds 4 rows ----
        #pragma unroll
        for (int jj = 0; jj < TJ; jj++) {
            const u64 wv = *reinterpret_cast<const u64*>(&wxj[jj][lane * 2]);
            u64 pa2, pb2, pc2, pd2;
            lds_v2u64(pa2, pb2, &p_ab[w][jj]);
            lds_v2u64(pc2, pd2, &p_cd[w][jj]);
            fma2(accA, pa2, wv);
            fma2(accB, pb2, wv);
            fma2(accC, pc2, wv);
            fma2(accD, pd2, wv);
        }
        __syncwarp();   // agg done before next tile's p overwrite
    }

    // ---- reduce per-lane s partials across the warp ----
    #pragma unroll
    for (int off = 16; off > 0; off >>= 1) {
        sA += __shfl_xor_sync(0xffffffffu, sA, off);
        sB += __shfl_xor_sync(0xffffffffu, sB, off);
        sC += __shfl_xor_sync(0xffffffffu, sC, off);
        sD += __shfl_xor_sync(0xffffffffu, sD, off);
    }

    // ---- write partials (unnormalized) ----
    const int gA = rA * H + h, gB = rB * H + h, gC = rC * H + h, gD = rD * H + h;
    if (lane == 0) {
        g_pm[gA][sp] = mA; g_ps[gA][sp] = sA;
        g_pm[gB][sp] = mB; g_ps[gB][sp] = sB;
        g_pm[gC][sp] = mC; g_ps[gC][sp] = sC;
        g_pm[gD][sp] = mD; g_ps[gD][sp] = sD;
    }
    float2 o;
    o = upk2(accA); *reinterpret_cast<float2*>(&g_pacc[gA][sp][2 * lane]) = o;
    o = upk2(accB); *reinterpret_cast<float2*>(&g_pacc[gB][sp][2 * lane]) = o;
    o = upk2(accC); *reinterpret_cast<float2*>(&g_pacc[gC][sp][2 * lane]) = o;
    o = upk2(accD); *reinterpret_cast<float2*>(&g_pacc[gD][sp][2 * lane]) = o;
}

// ---------------------------------------------------------------------------
// Combine: merge NSPLIT partial softmaxes per (i,h) row. Warp per row.
// ---------------------------------------------------------------------------
__global__ __launch_bounds__(256) void combine_kernel(float* __restrict__ out) {
    const int tid  = threadIdx.x;
    const int w    = tid / 32;
    const int lane = tid % 32;
    const int r    = blockIdx.x * 8 + w;     // 0..3071
    const int i    = r / H;
    const int h    = r % H;

    float mp = (lane < NSPLIT) ? g_pm[r][lane] : -1e30f;
    float ms = mp;
    #pragma unroll
    for (int off = 16; off > 0; off >>= 1)
        ms = fmaxf(ms, __shfl_xor_sync(0xffffffffu, ms, off));
    float fac = (lane < NSPLIT) ? __expf(mp - ms) : 0.f;
    float sv  = (lane < NSPLIT) ? g_ps[r][lane] * fac : 0.f;
    #pragma unroll
    for (int off = 16; off > 0; off >>= 1)
        sv += __shfl_xor_sync(0xffffffffu, sv, off);

    float facs[NSPLIT];
    #pragma unroll
    for (int q = 0; q < NSPLIT; q++)
        facs[q] = __shfl_sync(0xffffffffu, fac, q);

    float ox = 0.f, oy = 0.f;
    #pragma unroll
    for (int q = 0; q < NSPLIT; q++) {
        float2 av = *reinterpret_cast<const float2*>(&g_pacc[r][q][2 * lane]);
        ox += av.x * facs[q];
        oy += av.y * facs[q];
    }
    const float inv = 1.f / sv;
    *reinterpret_cast<float2*>(&out[i * OUTD + h * FH + 2 * lane]) =
        make_float2(ox * inv, oy * inv);
}

// ---------------------------------------------------------------------------
extern "C" void kernel_launch(void* const* d_in, const int* in_sizes, int n_in,
                              void* d_out, int out_size) {
    const float* x = nullptr;
    const int*   adj = nullptr;
    const float* W = nullptr;
    const float* a = nullptr;
    for (int i = 0; i < n_in; i++) {
        switch (in_sizes[i]) {
            case N_NODES * INP:      x   = (const float*)d_in[i]; break;
            case N_NODES * N_NODES:  adj = (const int*)d_in[i];   break;
            case OUTD * INP:         W   = (const float*)d_in[i]; break;
            case FH:                 a   = (const float*)d_in[i]; break;
            default: break;
        }
    }
    float* out = (float*)d_out;

    dim3 gg(H, N_NODES / 16);                     // 4 x 48 = 192 blocks
    gemm_kernel<<<gg, 256>>>(x, W, a);
    dim3 ga((N_NODES / TI) * NSPLIT, H);          // 288 x 4 = 1152 blocks
    attn_kernel<<<ga, 128>>>(adj, a);
    combine_kernel<<<N_NODES * H / 8, 256>>>(out);   // 384 blocks
}

// round 9
// speedup vs baseline: 1.0382x; 1.0382x over previous
#include <cuda_runtime.h>

#define N_NODES 768
#define INP     256
#define H       4
#define FH      64
#define OUTD    256   // H*FH
#define NSPLIT  4
#define JSPAN   (N_NODES / NSPLIT)   // 192
#define TI      16
#define TJ      64
#define WXJ_PAD 70

typedef unsigned long long u64;

// Scratch (no cudaMalloc allowed)
__device__ float g_Wx[N_NODES * OUTD];
__device__ float g_E[N_NODES * H];
__device__ float g_pm[N_NODES * H][NSPLIT];
__device__ float g_ps[N_NODES * H][NSPLIT];
__device__ float g_pacc[N_NODES * H][NSPLIT][FH];

// ---------------- packed f32x2 helpers (sm_103a) ----------------
__device__ __forceinline__ u64 pk2(float x, float y) {
    u64 r; asm("mov.b64 %0,{%1,%2};" : "=l"(r) : "f"(x), "f"(y)); return r;
}
__device__ __forceinline__ float2 upk2(u64 v) {
    float2 r; asm("mov.b64 {%0,%1},%2;" : "=f"(r.x), "=f"(r.y) : "l"(v)); return r;
}
__device__ __forceinline__ void mac_abs2(u64& acc, u64 av, u64 wi, u64 sj) {
    u64 t;
    asm("add.rn.f32x2 %0,%1,%2;" : "=l"(t) : "l"(wi), "l"(sj));
    asm("and.b64 %0,%0,0x7FFFFFFF7FFFFFFF;" : "+l"(t));
    asm("fma.rn.f32x2 %0,%1,%2,%0;" : "+l"(acc) : "l"(av), "l"(t));
}
__device__ __forceinline__ void fma2(u64& acc, u64 a, u64 b) {
    asm("fma.rn.f32x2 %0,%1,%2,%0;" : "+l"(acc) : "l"(a), "l"(b));
}
__device__ __forceinline__ void mul2(u64& acc, u64 a) {
    asm("mul.rn.f32x2 %0,%0,%1;" : "+l"(acc) : "l"(a));
}
// LDS.128 into two u64 (one broadcast feeds two packed operands)
__device__ __forceinline__ void lds_v2u64(u64& a, u64& b, const void* p) {
    unsigned s = (unsigned)__cvta_generic_to_shared(p);
    asm("ld.shared.v2.u64 {%0,%1}, [%2];" : "=l"(a), "=l"(b) : "r"(s));
}

// ---------------------------------------------------------------------------
// GEMM: Wx = x @ W^T.  BM=64, BN=64(=1 head), BK=32, 256 thr, 4x4 thread tile.
// Grid (H, 12) = 48 blocks — one wave; deep compute per sync phase hides
// prefetch latency. Register double-buffering. Fused E epilogue.
// ---------------------------------------------------------------------------
__global__ __launch_bounds__(256) void gemm_kernel(const float* __restrict__ x,
                                                   const float* __restrict__ W,
                                                   const float* __restrict__ a) {
    __shared__ float As[32][68];   // [k][m]
    __shared__ float Bs[32][68];   // [k][n]
    const int tid = threadIdx.x;
    const int h  = blockIdx.x;
    const int m0 = blockIdx.y * 64;
    const int n0 = h * 64;

    const int tx = tid % 16;       // n quad
    const int ty = tid / 16;       // m quad (0..15)
    float4 acc[4] = {};

    float4 px[2], pw[2];
    #pragma unroll
    for (int q = 0; q < 2; q++) {
        const int id = tid + q * 256;
        const int r = id / 8, c = id % 8;
        px[q] = *reinterpret_cast<const float4*>(&x[(m0 + r) * INP + c * 4]);
        pw[q] = *reinterpret_cast<const float4*>(&W[(n0 + r) * INP + c * 4]);
    }

    #pragma unroll 1
    for (int it = 0; it < 8; it++) {
        __syncthreads();
        #pragma unroll
        for (int q = 0; q < 2; q++) {
            const int id = tid + q * 256;
            const int r = id / 8, c = id % 8;
            As[c * 4 + 0][r] = px[q].x; As[c * 4 + 1][r] = px[q].y;
            As[c * 4 + 2][r] = px[q].z; As[c * 4 + 3][r] = px[q].w;
            Bs[c * 4 + 0][r] = pw[q].x; Bs[c * 4 + 1][r] = pw[q].y;
            Bs[c * 4 + 2][r] = pw[q].z; Bs[c * 4 + 3][r] = pw[q].w;
        }
        __syncthreads();
        if (it < 7) {
            const int k0 = (it + 1) * 32;
            #pragma unroll
            for (int q = 0; q < 2; q++) {
                const int id = tid + q * 256;
                const int r = id / 8, c = id % 8;
                px[q] = *reinterpret_cast<const float4*>(&x[(m0 + r) * INP + k0 + c * 4]);
                pw[q] = *reinterpret_cast<const float4*>(&W[(n0 + r) * INP + k0 + c * 4]);
            }
        }
        #pragma unroll
        for (int k = 0; k < 32; k++) {
            float4 av = *reinterpret_cast<const float4*>(&As[k][ty * 4]);
            float4 bv = *reinterpret_cast<const float4*>(&Bs[k][tx * 4]);
            acc[0].x += av.x * bv.x; acc[0].y += av.x * bv.y;
            acc[0].z += av.x * bv.z; acc[0].w += av.x * bv.w;
            acc[1].x += av.y * bv.x; acc[1].y += av.y * bv.y;
            acc[1].z += av.y * bv.z; acc[1].w += av.y * bv.w;
            acc[2].x += av.z * bv.x; acc[2].y += av.z * bv.y;
            acc[2].z += av.z * bv.z; acc[2].w += av.z * bv.w;
            acc[3].x += av.w * bv.x; acc[3].y += av.w * bv.y;
            acc[3].z += av.w * bv.z; acc[3].w += av.w * bv.w;
        }
    }

    float4 a4v = *reinterpret_cast<const float4*>(&a[tx * 4]);
    #pragma unroll
    for (int i = 0; i < 4; i++) {
        const int m = m0 + ty * 4 + i;
        *reinterpret_cast<float4*>(&g_Wx[m * OUTD + n0 + tx * 4]) = acc[i];
        float ev = a4v.x * acc[i].x + a4v.y * acc[i].y
                 + a4v.z * acc[i].z + a4v.w * acc[i].w;
        #pragma unroll
        for (int off = 1; off < 16; off <<= 1)
            ev += __shfl_xor_sync(0xffffffffu, ev, off);
        if (tx == 0) g_E[m * H + h] = ev;
    }
}

// ---------------------------------------------------------------------------
// Split-KV flash attention (round-6 proven body, verbatim).
// Block = (16 i-rows, head, j-split of 192). 128 threads, warp w owns rows
// {w, w+4, w+8, w+12}. Partial (m,s,acc) out.
// ---------------------------------------------------------------------------
__global__ __launch_bounds__(128) void attn_kernel(const int* __restrict__ adj,
                                                   const float* __restrict__ a) {
    __shared__ __align__(16) float wxj[TJ][WXJ_PAD];   // 17.9 KB
    __shared__ float4 wi4[2][4][32];                   // 4 KB: [q][warp][k] = 2 rows' f-pair
    __shared__ float4 p_ab[4][TJ];                     // 4 KB: (pa,pa,pb,pb)
    __shared__ float4 p_cd[4][TJ];                     // 4 KB
    __shared__ u64    av2[FH / 2];
    __shared__ float  e06s[JSPAN];                     // 0.6*E_j for this split

    const int tid  = threadIdx.x;
    const int w    = tid / 32;
    const int lane = tid % 32;
    const int h    = blockIdx.y;
    const int iblk = blockIdx.x >> 2;
    const int sp   = blockIdx.x & 3;
    const int i0   = iblk * TI;
    const int jbase = sp * JSPAN;

    // ---- stage per-block constants ----
    for (int id = tid; id < 256; id += 128) {          // wi4: 256 float4
        const int q = id >> 7, rem = id & 127;
        const int w2 = rem >> 5, k = rem & 31;
        const int r0 = w2 + 8 * q, r1 = r0 + 4;
        float2 lo = *reinterpret_cast<const float2*>(&g_Wx[(i0 + r0) * OUTD + h * FH + 2 * k]);
        float2 hi = *reinterpret_cast<const float2*>(&g_Wx[(i0 + r1) * OUTD + h * FH + 2 * k]);
        wi4[q][w2][k] = make_float4(lo.x, lo.y, hi.x, hi.y);
    }
    if (tid < FH / 2)
        av2[tid] = *reinterpret_cast<const u64*>(&a[2 * tid]);
    for (int id = tid; id < JSPAN; id += 128)
        e06s[id] = 0.6f * g_E[(jbase + id) * H + h];

    const int rA = i0 + w, rB = rA + 4, rC = rA + 8, rD = rA + 12;
    const float eiA = 0.6f * g_E[rA * H + h];
    const float eiB = 0.6f * g_E[rB * H + h];
    const float eiC = 0.6f * g_E[rC * H + h];
    const float eiD = 0.6f * g_E[rD * H + h];
    const int* adjA = &adj[rA * N_NODES + jbase];
    const int* adjB = &adj[rB * N_NODES + jbase];
    const int* adjC = &adj[rC * N_NODES + jbase];
    const int* adjD = &adj[rD * N_NODES + jbase];

    float mA = -1e30f, sA = 0.f, mB = -1e30f, sB = 0.f;
    float mC = -1e30f, sC = 0.f, mD = -1e30f, sD = 0.f;
    u64 accA = 0, accB = 0, accC = 0, accD = 0;

    for (int jt = 0; jt < JSPAN; jt += TJ) {
        __syncthreads();
        // ---- stage wxj tile (64 rows x 64 f): 1024 float4, 8/thread ----
        #pragma unroll
        for (int r = 0; r < 8; r++) {
            const int id = tid + r * 128;
            const int jj = id / 16, c4 = id % 16;
            float4 v = *reinterpret_cast<const float4*>(
                &g_Wx[(jbase + jt + jj) * OUTD + h * FH + c4 * 4]);
            *reinterpret_cast<float2*>(&wxj[jj][c4 * 4])     = make_float2(v.x, v.y);
            *reinterpret_cast<float2*>(&wxj[jj][c4 * 4 + 2]) = make_float2(v.z, v.w);
        }
        __syncthreads();

        // ---- e-phase: lane j-cols (jt+lane, jt+32+lane) x 4 rows ----
        const u64* wj0 = reinterpret_cast<const u64*>(&wxj[lane][0]);
        const u64* wj1 = reinterpret_cast<const u64*>(&wxj[lane + 32][0]);
        u64 eA0 = 0, eA1 = 0, eB0 = 0, eB1 = 0;
        u64 eC0 = 0, eC1 = 0, eD0 = 0, eD1 = 0;
        #pragma unroll
        for (int k = 0; k < 32; k++) {
            const u64 avk = av2[k];
            u64 wa, wb, wc, wd;
            lds_v2u64(wa, wb, &wi4[0][w][k]);
            lds_v2u64(wc, wd, &wi4[1][w][k]);
            const u64 j0 = wj0[k];
            const u64 j1 = wj1[k];
            mac_abs2(eA0, avk, wa, j0);  mac_abs2(eA1, avk, wa, j1);
            mac_abs2(eB0, avk, wb, j0);  mac_abs2(eB1, avk, wb, j1);
            mac_abs2(eC0, avk, wc, j0);  mac_abs2(eC1, avk, wc, j1);
            mac_abs2(eD0, avk, wd, j0);  mac_abs2(eD1, avk, wd, j1);
        }
        const float ej0 = e06s[jt + lane], ej1 = e06s[jt + 32 + lane];
        float2 f;
        f = upk2(eA0); float e_A0 = eiA + ej0 + 0.4f * (f.x + f.y);
        f = upk2(eA1); float e_A1 = eiA + ej1 + 0.4f * (f.x + f.y);
        f = upk2(eB0); float e_B0 = eiB + ej0 + 0.4f * (f.x + f.y);
        f = upk2(eB1); float e_B1 = eiB + ej1 + 0.4f * (f.x + f.y);
        f = upk2(eC0); float e_C0 = eiC + ej0 + 0.4f * (f.x + f.y);
        f = upk2(eC1); float e_C1 = eiC + ej1 + 0.4f * (f.x + f.y);
        f = upk2(eD0); float e_D0 = eiD + ej0 + 0.4f * (f.x + f.y);
        f = upk2(eD1); float e_D1 = eiD + ej1 + 0.4f * (f.x + f.y);
        if (adjA[jt + lane]      == 0) e_A0 = -1e30f;
        if (adjA[jt + 32 + lane] == 0) e_A1 = -1e30f;
        if (adjB[jt + lane]      == 0) e_B0 = -1e30f;
        if (adjB[jt + 32 + lane] == 0) e_B1 = -1e30f;
        if (adjC[jt + lane]      == 0) e_C0 = -1e30f;
        if (adjC[jt + 32 + lane] == 0) e_C1 = -1e30f;
        if (adjD[jt + lane]      == 0) e_D0 = -1e30f;
        if (adjD[jt + 32 + lane] == 0) e_D1 = -1e30f;

        // ---- online softmax update, 4 rows ----
        float tA = fmaxf(e_A0, e_A1), tB = fmaxf(e_B0, e_B1);
        float tC = fmaxf(e_C0, e_C1), tD = fmaxf(e_D0, e_D1);
        #pragma unroll
        for (int off = 16; off > 0; off >>= 1) {
            tA = fmaxf(tA, __shfl_xor_sync(0xffffffffu, tA, off));
            tB = fmaxf(tB, __shfl_xor_sync(0xffffffffu, tB, off));
            tC = fmaxf(tC, __shfl_xor_sync(0xffffffffu, tC, off));
            tD = fmaxf(tD, __shfl_xor_sync(0xffffffffu, tD, off));
        }
        const float nA = fmaxf(mA, tA), nB = fmaxf(mB, tB);
        const float nC = fmaxf(mC, tC), nD = fmaxf(mD, tD);
        const float scA = __expf(mA - nA), scB = __expf(mB - nB);
        const float scC = __expf(mC - nC), scD = __expf(mD - nD);
        const float pA0 = __expf(e_A0 - nA), pA1 = __expf(e_A1 - nA);
        const float pB0 = __expf(e_B0 - nB), pB1 = __expf(e_B1 - nB);
        const float pC0 = __expf(e_C0 - nC), pC1 = __expf(e_C1 - nC);
        const float pD0 = __expf(e_D0 - nD), pD1 = __expf(e_D1 - nD);
        sA = sA * scA + pA0 + pA1;  sB = sB * scB + pB0 + pB1;
        sC = sC * scC + pC0 + pC1;  sD = sD * scD + pD0 + pD1;
        mul2(accA, pk2(scA, scA));  mul2(accB, pk2(scB, scB));
        mul2(accC, pk2(scC, scC));  mul2(accD, pk2(scD, scD));
        mA = nA; mB = nB; mC = nC; mD = nD;

        p_ab[w][lane]      = make_float4(pA0, pA0, pB0, pB0);
        p_ab[w][lane + 32] = make_float4(pA1, pA1, pB1, pB1);
        p_cd[w][lane]      = make_float4(pC0, pC0, pD0, pD0);
        p_cd[w][lane + 32] = make_float4(pC1, pC1, pD1, pD1);
        __syncwarp();

        // ---- aggregation: one wv read feeds 4 rows ----
        #pragma unroll
        for (int jj = 0; jj < TJ; jj++) {
            const u64 wv = *reinterpret_cast<const u64*>(&wxj[jj][lane * 2]);
            u64 pa2, pb2, pc2, pd2;
            lds_v2u64(pa2, pb2, &p_ab[w][jj]);
            lds_v2u64(pc2, pd2, &p_cd[w][jj]);
            fma2(accA, pa2, wv);
            fma2(accB, pb2, wv);
            fma2(accC, pc2, wv);
            fma2(accD, pd2, wv);
        }
        __syncwarp();   // agg done before next tile's p overwrite
    }

    // ---- reduce per-lane s partials across the warp ----
    #pragma unroll
    for (int off = 16; off > 0; off >>= 1) {
        sA += __shfl_xor_sync(0xffffffffu, sA, off);
        sB += __shfl_xor_sync(0xffffffffu, sB, off);
        sC += __shfl_xor_sync(0xffffffffu, sC, off);
        sD += __shfl_xor_sync(0xffffffffu, sD, off);
    }

    // ---- write partials (unnormalized) ----
    const int gA = rA * H + h, gB = rB * H + h, gC = rC * H + h, gD = rD * H + h;
    if (lane == 0) {
        g_pm[gA][sp] = mA; g_ps[gA][sp] = sA;
        g_pm[gB][sp] = mB; g_ps[gB][sp] = sB;
        g_pm[gC][sp] = mC; g_ps[gC][sp] = sC;
        g_pm[gD][sp] = mD; g_ps[gD][sp] = sD;
    }
    float2 o;
    o = upk2(accA); *reinterpret_cast<float2*>(&g_pacc[gA][sp][2 * lane]) = o;
    o = upk2(accB); *reinterpret_cast<float2*>(&g_pacc[gB][sp][2 * lane]) = o;
    o = upk2(accC); *reinterpret_cast<float2*>(&g_pacc[gC][sp][2 * lane]) = o;
    o = upk2(accD); *reinterpret_cast<float2*>(&g_pacc[gD][sp][2 * lane]) = o;
}

// ---------------------------------------------------------------------------
// Combine: merge NSPLIT partial softmaxes per (i,h) row. Warp per row.
// ---------------------------------------------------------------------------
__global__ __launch_bounds__(256) void combine_kernel(float* __restrict__ out) {
    const int tid  = threadIdx.x;
    const int w    = tid / 32;
    const int lane = tid % 32;
    const int r    = blockIdx.x * 8 + w;     // 0..3071
    const int i    = r / H;
    const int h    = r % H;

    float mp = (lane < NSPLIT) ? g_pm[r][lane] : -1e30f;
    float ms = mp;
    #pragma unroll
    for (int off = 16; off > 0; off >>= 1)
        ms = fmaxf(ms, __shfl_xor_sync(0xffffffffu, ms, off));
    float fac = (lane < NSPLIT) ? __expf(mp - ms) : 0.f;
    float sv  = (lane < NSPLIT) ? g_ps[r][lane] * fac : 0.f;
    #pragma unroll
    for (int off = 16; off > 0; off >>= 1)
        sv += __shfl_xor_sync(0xffffffffu, sv, off);
    const float f0 = __shfl_sync(0xffffffffu, fac, 0);
    const float f1 = __shfl_sync(0xffffffffu, fac, 1);
    const float f2 = __shfl_sync(0xffffffffu, fac, 2);
    const float f3 = __shfl_sync(0xffffffffu, fac, 3);

    float2 a0 = *reinterpret_cast<const float2*>(&g_pacc[r][0][2 * lane]);
    float2 a1 = *reinterpret_cast<const float2*>(&g_pacc[r][1][2 * lane]);
    float2 a2 = *reinterpret_cast<const float2*>(&g_pacc[r][2][2 * lane]);
    float2 a3 = *reinterpret_cast<const float2*>(&g_pacc[r][3][2 * lane]);
    const float inv = 1.f / sv;
    float ox = (a0.x * f0 + a1.x * f1 + a2.x * f2 + a3.x * f3) * inv;
    float oy = (a0.y * f0 + a1.y * f1 + a2.y * f2 + a3.y * f3) * inv;
    *reinterpret_cast<float2*>(&out[i * OUTD + h * FH + 2 * lane]) = make_float2(ox, oy);
}

// ---------------------------------------------------------------------------
extern "C" void kernel_launch(void* const* d_in, const int* in_sizes, int n_in,
                              void* d_out, int out_size) {
    const float* x = nullptr;
    const int*   adj = nullptr;
    const float* W = nullptr;
    const float* a = nullptr;
    for (int i = 0; i < n_in; i++) {
        switch (in_sizes[i]) {
            case N_NODES * INP:      x   = (const float*)d_in[i]; break;
            case N_NODES * N_NODES:  adj = (const int*)d_in[i];   break;
            case OUTD * INP:         W   = (const float*)d_in[i]; break;
            case FH:                 a   = (const float*)d_in[i]; break;
            default: break;
        }
    }
    float* out = (float*)d_out;

    dim3 gg(H, N_NODES / 64);                     // 4 x 12 = 48 blocks
    gemm_kernel<<<gg, 256>>>(x, W, a);
    dim3 ga((N_NODES / TI) * NSPLIT, H);          // 192 x 4 = 768 blocks
    attn_kernel<<<ga, 128>>>(adj, a);
    combine_kernel<<<N_NODES * H / 8, 256>>>(out);   // 384 blocks
}